// round 2
// baseline (speedup 1.0000x reference)
#include <cuda_runtime.h>

#define NN 25000
#define NE 400000
#define TE 256

// scratch (allocation-free rule: __device__ globals)
__device__ __align__(16) float g_Ai[NN * 8];
__device__ float g_cnt[NN];

__device__ __forceinline__ float silu_f(float v) {
    return v * __fdividef(1.0f, 1.0f + __expf(-v));
}

// ---------------------------------------------------------------- zero
__global__ void zero_kernel(float* __restrict__ out) {
    int i = blockIdx.x * 256 + threadIdx.x;
    if (i < NN * 40) out[i] = 0.0f;
    if (i < NN) g_cnt[i] = 0.0f;
}

// ---------------------------------------------------------------- atom MLP 16->64->32->8
__global__ void atom_kernel(const float* __restrict__ atom_table,
                            const float* __restrict__ fw1, const float* __restrict__ fb1,
                            const float* __restrict__ fw2, const float* __restrict__ fb2,
                            const float* __restrict__ fw3, const float* __restrict__ fb3,
                            const int* __restrict__ A)
{
    __shared__ float s[1024 + 64 + 2048 + 32 + 256 + 8];
    float* sW1 = s;             float* sB1 = sW1 + 1024;
    float* sW2 = sB1 + 64;      float* sB2 = sW2 + 2048;
    float* sW3 = sB2 + 32;      float* sB3 = sW3 + 256;
    int tid = threadIdx.x;
    for (int i = tid; i < 1024; i += 256) sW1[i] = fw1[i];
    for (int i = tid; i < 2048; i += 256) sW2[i] = fw2[i];
    if (tid < 256) { /* fw3 */ }
    for (int i = tid; i < 256; i += 256) sW3[i] = fw3[i];
    if (tid < 64) sB1[tid] = fb1[tid];
    if (tid < 32) sB2[tid] = fb2[tid];
    if (tid < 8)  sB3[tid] = fb3[tid];
    __syncthreads();

    int n = blockIdx.x * 256 + tid;
    if (n >= NN) return;

    float e[16];
    const float* at = atom_table + A[n] * 16;
    #pragma unroll
    for (int i = 0; i < 16; i++) e[i] = at[i];

    float h1[64];
    #pragma unroll
    for (int k = 0; k < 64; k++) {
        float a = sB1[k];
        #pragma unroll
        for (int i = 0; i < 16; i++) a = fmaf(e[i], sW1[i * 64 + k], a);
        h1[k] = silu_f(a);
    }
    float h2[32];
    #pragma unroll
    for (int k = 0; k < 32; k++) {
        float a = sB2[k];
        #pragma unroll
        for (int i = 0; i < 64; i++) a = fmaf(h1[i], sW2[i * 32 + k], a);
        h2[k] = silu_f(a);
    }
    #pragma unroll
    for (int k = 0; k < 8; k++) {
        float a = sB3[k];
        #pragma unroll
        for (int i = 0; i < 32; i++) a = fmaf(h2[i], sW3[i * 8 + k], a);
        g_Ai[n * 8 + k] = a;
    }
}

// ---------------------------------------------------------------- 64x64 layer helper (in regs, weights transposed in smem)
__device__ __forceinline__ void layer64(const float* __restrict__ Wt,
                                        const float* __restrict__ Bv,
                                        const float (&in)[64], float (&outv)[64])
{
    #pragma unroll
    for (int k = 0; k < 64; k++) {
        const float* wr = Wt + k * 64;
        float a0 = Bv[k], a1 = 0.f, a2 = 0.f, a3 = 0.f;
        #pragma unroll
        for (int i = 0; i < 64; i += 16) {
            float4 w0 = *(const float4*)(wr + i);
            float4 w1 = *(const float4*)(wr + i + 4);
            float4 w2 = *(const float4*)(wr + i + 8);
            float4 w3 = *(const float4*)(wr + i + 12);
            a0 = fmaf(w0.x, in[i+0], a0);  a0 = fmaf(w0.y, in[i+1], a0);
            a0 = fmaf(w0.z, in[i+2], a0);  a0 = fmaf(w0.w, in[i+3], a0);
            a1 = fmaf(w1.x, in[i+4], a1);  a1 = fmaf(w1.y, in[i+5], a1);
            a1 = fmaf(w1.z, in[i+6], a1);  a1 = fmaf(w1.w, in[i+7], a1);
            a2 = fmaf(w2.x, in[i+8], a2);  a2 = fmaf(w2.y, in[i+9], a2);
            a2 = fmaf(w2.z, in[i+10], a2); a2 = fmaf(w2.w, in[i+11], a2);
            a3 = fmaf(w3.x, in[i+12], a3); a3 = fmaf(w3.y, in[i+13], a3);
            a3 = fmaf(w3.z, in[i+14], a3); a3 = fmaf(w3.w, in[i+15], a3);
        }
        outv[k] = silu_f((a0 + a1) + (a2 + a3));
    }
}

// ---------------------------------------------------------------- fused last layer chunk: W_c then g accumulation
template<int MUL, int GB>
__device__ __forceinline__ void chunk_accum(const float* __restrict__ sChunk,
                                            const float* __restrict__ sBias,
                                            const float* __restrict__ sAs,
                                            const float* __restrict__ sAd,
                                            int tid, int pair_base,
                                            const float (&h3)[64], float (&g)[16])
{
    const int NP = 128 / MUL;
    #pragma unroll 1
    for (int p = 0; p < NP; p++) {
        int ij = pair_base + p;
        float pij = sAs[(ij >> 3) * TE + tid] * sAd[(ij & 7) * TE + tid];
        const float* colb = sChunk + p * MUL * 68;
        #pragma unroll
        for (int u = 0; u < MUL; u++) {
            const float* col = colb + u * 68;
            float a0 = 0.f, a1 = 0.f, a2 = 0.f, a3 = 0.f;
            #pragma unroll
            for (int k = 0; k < 64; k += 16) {
                float4 w0 = *(const float4*)(col + k);
                float4 w1 = *(const float4*)(col + k + 4);
                float4 w2 = *(const float4*)(col + k + 8);
                float4 w3 = *(const float4*)(col + k + 12);
                a0 = fmaf(w0.x, h3[k+0], a0);  a0 = fmaf(w0.y, h3[k+1], a0);
                a0 = fmaf(w0.z, h3[k+2], a0);  a0 = fmaf(w0.w, h3[k+3], a0);
                a1 = fmaf(w1.x, h3[k+4], a1);  a1 = fmaf(w1.y, h3[k+5], a1);
                a1 = fmaf(w1.z, h3[k+6], a1);  a1 = fmaf(w1.w, h3[k+7], a1);
                a2 = fmaf(w2.x, h3[k+8], a2);  a2 = fmaf(w2.y, h3[k+9], a2);
                a2 = fmaf(w2.z, h3[k+10], a2); a2 = fmaf(w2.w, h3[k+11], a2);
                a3 = fmaf(w3.x, h3[k+12], a3); a3 = fmaf(w3.y, h3[k+13], a3);
                a3 = fmaf(w3.z, h3[k+14], a3); a3 = fmaf(w3.w, h3[k+15], a3);
            }
            float W = sBias[p * MUL + u] + ((a0 + a1) + (a2 + a3));
            g[GB + u] = fmaf(pij, W, g[GB + u]);
        }
    }
}

// ---------------------------------------------------------------- main edge kernel
__global__ void __launch_bounds__(TE) edge_kernel(
    const float* __restrict__ pos, const float* __restrict__ shifts,
    const float* __restrict__ cell,
    const float* __restrict__ gw1, const float* __restrict__ gb1,
    const float* __restrict__ gw2, const float* __restrict__ gb2,
    const float* __restrict__ gw3, const float* __restrict__ gb3,
    const float* __restrict__ gw4, const float* __restrict__ gb4,
    const int* __restrict__ batch,
    const int* __restrict__ esrc, const int* __restrict__ edst,
    float* __restrict__ out)
{
    extern __shared__ float sm[];
    float* sG1T  = sm;              // 512  [k][i] transposed
    float* sB1   = sG1T + 512;      // 64
    float* sG2T  = sB1 + 64;        // 4096 [k][i]
    float* sB2   = sG2T + 4096;     // 64
    float* sG3T  = sB2 + 64;        // 4096
    float* sB3   = sG3T + 4096;     // 64
    float* sAs   = sB3 + 64;        // 8*TE  [feat][tid]
    float* sAd   = sAs + 8 * TE;    // 8*TE
    float* sBias = sAd + 8 * TE;    // 128
    float* sChunk = sBias + 128;    // 128*68 column-major [c][k], stride 68

    int tid = threadIdx.x;
    // stage small MLP weights (transposed for vectorized k-dot)
    for (int idx = tid; idx < 512; idx += TE) {
        int i = idx >> 6, k = idx & 63;
        sG1T[k * 8 + i] = gw1[idx];
    }
    for (int idx = tid; idx < 4096; idx += TE) {
        int i = idx >> 6, k = idx & 63;
        sG2T[k * 64 + i] = gw2[idx];
        sG3T[k * 64 + i] = gw3[idx];
    }
    if (tid < 64) { sB1[tid] = gb1[tid]; sB2[tid] = gb2[tid]; sB3[tid] = gb3[tid]; }

    int e = blockIdx.x * TE + tid;
    bool valid = e < NE;
    int ee = valid ? e : 0;
    int src = esrc[ee], dst = edst[ee];

    // edge vector (with shift @ cell)
    float s0 = shifts[ee * 3 + 0], s1 = shifts[ee * 3 + 1], s2 = shifts[ee * 3 + 2];
    const float* cb = cell + batch[src] * 9;
    float vx = pos[dst * 3 + 0] - pos[src * 3 + 0] + s0 * cb[0] + s1 * cb[3] + s2 * cb[6];
    float vy = pos[dst * 3 + 1] - pos[src * 3 + 1] + s0 * cb[1] + s1 * cb[4] + s2 * cb[7];
    float vz = pos[dst * 3 + 2] - pos[src * 3 + 2] + s0 * cb[2] + s1 * cb[5] + s2 * cb[8];
    float r  = sqrtf(vx * vx + vy * vy + vz * vz + 1e-12f);
    float ir = __fdividef(1.0f, r);
    float ux = vx * ir, uy = vy * ir, uz = vz * ir;

    // spherical harmonics l=0,1,2
    float sh[9];
    sh[0] = 1.0f;
    sh[1] = 1.7320508075688772f * ux;
    sh[2] = 1.7320508075688772f * uy;
    sh[3] = 1.7320508075688772f * uz;
    sh[4] = 3.872983346207417f * ux * uy;
    sh[5] = 3.872983346207417f * uy * uz;
    sh[6] = 1.118033988749895f * (2.0f * uz * uz - ux * ux - uy * uy);
    sh[7] = 3.872983346207417f * ux * uz;
    sh[8] = 1.9364916731037085f * (ux * ux - uy * uy);

    // radial gaussian embedding (NB=8, sigma=1/7, * sqrt(8), cutoff)
    float xr = fminf(r * 0.2f, 1.0f);
    float mk = (r <= 5.0f) ? 2.8284271247461903f : 0.0f;
    float emb[8];
    #pragma unroll
    for (int j = 0; j < 8; j++) {
        float t = (xr - (float)j * (1.0f / 7.0f)) * 7.0f;
        emb[j] = __expf(-0.5f * t * t) * mk;
    }

    // gathered atom features -> smem ([feat][tid], self-read only)
    float4 as0 = *(const float4*)(g_Ai + src * 8);
    float4 as1 = *(const float4*)(g_Ai + src * 8 + 4);
    float4 ad0 = *(const float4*)(g_Ai + dst * 8);
    float4 ad1 = *(const float4*)(g_Ai + dst * 8 + 4);
    sAs[0 * TE + tid] = as0.x; sAs[1 * TE + tid] = as0.y; sAs[2 * TE + tid] = as0.z; sAs[3 * TE + tid] = as0.w;
    sAs[4 * TE + tid] = as1.x; sAs[5 * TE + tid] = as1.y; sAs[6 * TE + tid] = as1.z; sAs[7 * TE + tid] = as1.w;
    sAd[0 * TE + tid] = ad0.x; sAd[1 * TE + tid] = ad0.y; sAd[2 * TE + tid] = ad0.z; sAd[3 * TE + tid] = ad0.w;
    sAd[4 * TE + tid] = ad1.x; sAd[5 * TE + tid] = ad1.y; sAd[6 * TE + tid] = ad1.z; sAd[7 * TE + tid] = ad1.w;

    __syncthreads();   // weight staging complete

    // radial MLP layers 1..3 (register-resident, broadcast smem weights)
    float h1[64];
    #pragma unroll
    for (int k = 0; k < 64; k++) {
        const float4* w = (const float4*)(sG1T + k * 8);
        float4 w0 = w[0], w1 = w[1];
        float a = sB1[k];
        a = fmaf(w0.x, emb[0], a); a = fmaf(w0.y, emb[1], a);
        a = fmaf(w0.z, emb[2], a); a = fmaf(w0.w, emb[3], a);
        a = fmaf(w1.x, emb[4], a); a = fmaf(w1.y, emb[5], a);
        a = fmaf(w1.z, emb[6], a); a = fmaf(w1.w, emb[7], a);
        h1[k] = silu_f(a);
    }
    float h2[64];
    layer64(sG2T, sB2, h1, h2);
    float h3[64];
    layer64(sG3T, sB3, h2, h3);

    // fused final layer + tensor-product contraction over 8 gw4 chunks
    float g[16];
    #pragma unroll
    for (int i = 0; i < 16; i++) g[i] = 0.f;

    #pragma unroll 1
    for (int ch = 0; ch < 8; ch++) {
        __syncthreads();                 // previous chunk fully consumed
        int cbase = ch << 7;
        #pragma unroll
        for (int t2 = 0; t2 < 32; t2++) {  // 64*128/TE
            int idx = t2 * TE + tid;
            int k = idx >> 7, c = idx & 127;
            sChunk[c * 68 + k] = gw4[k * 1024 + cbase + c];   // coalesced read, ~4-way STS conflict (negligible)
        }
        if (tid < 128) sBias[tid] = gb4[cbase + tid];
        __syncthreads();

        if (ch < 4)       chunk_accum<8, 0>(sChunk, sBias, sAs, sAd, tid, ch * 16, h3, g);
        else if (ch < 6)  chunk_accum<4, 8>(sChunk, sBias, sAs, sAd, tid, (ch - 4) * 32, h3, g);
        else              chunk_accum<4, 12>(sChunk, sBias, sAs, sAd, tid, (ch - 6) * 32, h3, g);
    }

    // scatter: edge_features = alpha * g[u] * sh[m]
    if (valid) {
        float* o = out + dst * 40;
        const float alpha = 0.125f;
        #pragma unroll
        for (int u = 0; u < 8; u++) atomicAdd(o + u, alpha * g[u]);            // sh[0] = 1
        #pragma unroll
        for (int u = 0; u < 4; u++)
            #pragma unroll
            for (int m = 0; m < 3; m++)
                atomicAdd(o + 8 + u * 3 + m, alpha * g[8 + u] * sh[1 + m]);
        #pragma unroll
        for (int u = 0; u < 4; u++)
            #pragma unroll
            for (int m = 0; m < 5; m++)
                atomicAdd(o + 20 + u * 5 + m, alpha * g[12 + u] * sh[4 + m]);
        atomicAdd(&g_cnt[dst], 1.0f);
    }
}

// ---------------------------------------------------------------- normalize (segment mean)
__global__ void norm_kernel(float* __restrict__ out) {
    int i = blockIdx.x * 256 + threadIdx.x;
    if (i < NN * 40) {
        float c = g_cnt[i / 40];
        out[i] = out[i] / fmaxf(c, 1.0f);
    }
}

// ---------------------------------------------------------------- launch
extern "C" void kernel_launch(void* const* d_in, const int* in_sizes, int n_in,
                              void* d_out, int out_size)
{
    const float* pos        = (const float*)d_in[0];
    const float* shifts     = (const float*)d_in[1];
    const float* cell       = (const float*)d_in[2];
    const float* atom_table = (const float*)d_in[3];
    const float* fw1 = (const float*)d_in[4];  const float* fb1 = (const float*)d_in[5];
    const float* fw2 = (const float*)d_in[6];  const float* fb2 = (const float*)d_in[7];
    const float* fw3 = (const float*)d_in[8];  const float* fb3 = (const float*)d_in[9];
    const float* gw1 = (const float*)d_in[10]; const float* gb1 = (const float*)d_in[11];
    const float* gw2 = (const float*)d_in[12]; const float* gb2 = (const float*)d_in[13];
    const float* gw3 = (const float*)d_in[14]; const float* gb3 = (const float*)d_in[15];
    const float* gw4 = (const float*)d_in[16]; const float* gb4 = (const float*)d_in[17];
    const int* A     = (const int*)d_in[18];
    const int* batch = (const int*)d_in[19];
    const int* esrc  = (const int*)d_in[20];
    const int* edst  = (const int*)d_in[21];
    float* out = (float*)d_out;

    const int SMEM_EDGE = 21824 * 4;  // 87296 bytes
    cudaFuncSetAttribute(edge_kernel, cudaFuncAttributeMaxDynamicSharedMemorySize, SMEM_EDGE);

    zero_kernel<<<(NN * 40 + 255) / 256, 256>>>(out);
    atom_kernel<<<(NN + 255) / 256, 256>>>(atom_table, fw1, fb1, fw2, fb2, fw3, fb3, A);
    edge_kernel<<<(NE + TE - 1) / TE, TE, SMEM_EDGE>>>(pos, shifts, cell,
                                                       gw1, gb1, gw2, gb2, gw3, gb3, gw4, gb4,
                                                       batch, esrc, edst, out);
    norm_kernel<<<(NN * 40 + 255) / 256, 256>>>(out);
}

// round 3
// speedup vs baseline: 1.1173x; 1.1173x over previous
#include <cuda_runtime.h>

#define NN 25000
#define NE 400000
#define TE 256

typedef unsigned long long u64;

// scratch (allocation-free rule: __device__ globals)
__device__ __align__(16) float g_Ai[NN * 8];
__device__ float g_cnt[NN];

__device__ __forceinline__ float silu_f(float v) {
    return v * __fdividef(1.0f, 1.0f + __expf(-v));
}

// ---- packed f32x2 primitives (Blackwell full-rate fp32 path) ----
__device__ __forceinline__ u64 f2fma(u64 a, u64 b, u64 c) {
    u64 d; asm("fma.rn.f32x2 %0,%1,%2,%3;" : "=l"(d) : "l"(a), "l"(b), "l"(c)); return d;
}
__device__ __forceinline__ u64 f2mul(u64 a, u64 b) {
    u64 d; asm("mul.rn.f32x2 %0,%1,%2;" : "=l"(d) : "l"(a), "l"(b)); return d;
}
__device__ __forceinline__ u64 f2add(u64 a, u64 b) {
    u64 d; asm("add.rn.f32x2 %0,%1,%2;" : "=l"(d) : "l"(a), "l"(b)); return d;
}
__device__ __forceinline__ u64 fpack(float lo, float hi) {
    u64 d; asm("mov.b64 %0,{%1,%2};" : "=l"(d) : "f"(lo), "f"(hi)); return d;
}
__device__ __forceinline__ float2 funpack(u64 v) {
    float lo, hi; asm("mov.b64 {%0,%1},%2;" : "=f"(lo), "=f"(hi) : "l"(v));
    return make_float2(lo, hi);
}

// ---------------------------------------------------------------- zero
__global__ void zero_kernel(float* __restrict__ out) {
    int i = blockIdx.x * 256 + threadIdx.x;
    if (i < NN * 40) out[i] = 0.0f;
    if (i < NN) g_cnt[i] = 0.0f;
}

// ---------------------------------------------------------------- atom MLP 16->64->32->8 (negligible cost; unchanged)
__global__ void atom_kernel(const float* __restrict__ atom_table,
                            const float* __restrict__ fw1, const float* __restrict__ fb1,
                            const float* __restrict__ fw2, const float* __restrict__ fb2,
                            const float* __restrict__ fw3, const float* __restrict__ fb3,
                            const int* __restrict__ A)
{
    __shared__ float s[1024 + 64 + 2048 + 32 + 256 + 8];
    float* sW1 = s;             float* sB1 = sW1 + 1024;
    float* sW2 = sB1 + 64;      float* sB2 = sW2 + 2048;
    float* sW3 = sB2 + 32;      float* sB3 = sW3 + 256;
    int tid = threadIdx.x;
    for (int i = tid; i < 1024; i += 256) sW1[i] = fw1[i];
    for (int i = tid; i < 2048; i += 256) sW2[i] = fw2[i];
    for (int i = tid; i < 256; i += 256) sW3[i] = fw3[i];
    if (tid < 64) sB1[tid] = fb1[tid];
    if (tid < 32) sB2[tid] = fb2[tid];
    if (tid < 8)  sB3[tid] = fb3[tid];
    __syncthreads();

    int n = blockIdx.x * 256 + tid;
    if (n >= NN) return;

    float e[16];
    const float* at = atom_table + A[n] * 16;
    #pragma unroll
    for (int i = 0; i < 16; i++) e[i] = at[i];

    float h1[64];
    #pragma unroll
    for (int k = 0; k < 64; k++) {
        float a = sB1[k];
        #pragma unroll
        for (int i = 0; i < 16; i++) a = fmaf(e[i], sW1[i * 64 + k], a);
        h1[k] = silu_f(a);
    }
    float h2[32];
    #pragma unroll
    for (int k = 0; k < 32; k++) {
        float a = sB2[k];
        #pragma unroll
        for (int i = 0; i < 64; i++) a = fmaf(h1[i], sW2[i * 32 + k], a);
        h2[k] = silu_f(a);
    }
    #pragma unroll
    for (int k = 0; k < 8; k++) {
        float a = sB3[k];
        #pragma unroll
        for (int i = 0; i < 32; i++) a = fmaf(h2[i], sW3[i * 8 + k], a);
        g_Ai[n * 8 + k] = a;
    }
}

// ---------------------------------------------------------------- 64x64 layer, packed over K
// Wt: row k = 64 contiguous input-weights. in: 32 packed pairs. outp: 32 packed outputs.
__device__ __forceinline__ void layer64p(const float* __restrict__ Wt,
                                         const float* __restrict__ Bv,
                                         const u64 (&in)[32], u64 (&outp)[32])
{
    #pragma unroll
    for (int k = 0; k < 64; k += 2) {
        float o[2];
        #pragma unroll
        for (int kk = 0; kk < 2; kk++) {
            const u64* wr = (const u64*)(Wt + (k + kk) * 64);
            ulonglong2 w01 = *(const ulonglong2*)(wr);
            ulonglong2 w23 = *(const ulonglong2*)(wr + 2);
            u64 a0 = f2mul(w01.x, in[0]);
            u64 a1 = f2mul(w01.y, in[1]);
            u64 a2 = f2mul(w23.x, in[2]);
            u64 a3 = f2mul(w23.y, in[3]);
            #pragma unroll
            for (int i = 4; i < 32; i += 4) {
                ulonglong2 v01 = *(const ulonglong2*)(wr + i);
                ulonglong2 v23 = *(const ulonglong2*)(wr + i + 2);
                a0 = f2fma(v01.x, in[i + 0], a0);
                a1 = f2fma(v01.y, in[i + 1], a1);
                a2 = f2fma(v23.x, in[i + 2], a2);
                a3 = f2fma(v23.y, in[i + 3], a3);
            }
            u64 s = f2add(f2add(a0, a1), f2add(a2, a3));
            float2 sv = funpack(s);
            o[kk] = silu_f(sv.x + sv.y + Bv[k + kk]);
        }
        outp[k >> 1] = fpack(o[0], o[1]);
    }
}

// ---------------------------------------------------------------- fused last layer chunk (packed)
// Per column: packed dot(h3, col) with bias folded into acc0 init;
// result stays PACKED, folded into packed g via one f32x2 FMA with (pij,pij).
template<int MUL, int GB>
__device__ __forceinline__ void chunk_accum(const float* __restrict__ sChunk,
                                            const float* __restrict__ sBias,
                                            const float* __restrict__ sAs,
                                            const float* __restrict__ sAd,
                                            int tid, int pair_base,
                                            const u64 (&h3)[32], u64 (&g)[16])
{
    const int NP = 128 / MUL;
    #pragma unroll 1
    for (int p = 0; p < NP; p++) {
        int ij = pair_base + p;
        float pij = sAs[(ij >> 3) * TE + tid] * sAd[(ij & 7) * TE + tid];
        u64 pijp = fpack(pij, pij);
        const float* colb = sChunk + p * MUL * 68;
        #pragma unroll
        for (int u = 0; u < MUL; u++) {
            const u64* col = (const u64*)(colb + u * 68);
            ulonglong2 w01 = *(const ulonglong2*)(col);
            ulonglong2 w23 = *(const ulonglong2*)(col + 2);
            u64 a0 = f2fma(w01.x, h3[0], fpack(sBias[p * MUL + u], 0.0f));
            u64 a1 = f2mul(w01.y, h3[1]);
            u64 a2 = f2mul(w23.x, h3[2]);
            u64 a3 = f2mul(w23.y, h3[3]);
            #pragma unroll
            for (int i = 4; i < 32; i += 4) {
                ulonglong2 v01 = *(const ulonglong2*)(col + i);
                ulonglong2 v23 = *(const ulonglong2*)(col + i + 2);
                a0 = f2fma(v01.x, h3[i + 0], a0);
                a1 = f2fma(v01.y, h3[i + 1], a1);
                a2 = f2fma(v23.x, h3[i + 2], a2);
                a3 = f2fma(v23.y, h3[i + 3], a3);
            }
            u64 s = f2add(f2add(a0, a1), f2add(a2, a3));
            g[GB + u] = f2fma(pijp, s, g[GB + u]);
        }
    }
}

// ---------------------------------------------------------------- main edge kernel
__global__ void __launch_bounds__(TE) edge_kernel(
    const float* __restrict__ pos, const float* __restrict__ shifts,
    const float* __restrict__ cell,
    const float* __restrict__ gw1, const float* __restrict__ gb1,
    const float* __restrict__ gw2, const float* __restrict__ gb2,
    const float* __restrict__ gw3, const float* __restrict__ gb3,
    const float* __restrict__ gw4, const float* __restrict__ gb4,
    const int* __restrict__ batch,
    const int* __restrict__ esrc, const int* __restrict__ edst,
    float* __restrict__ out)
{
    extern __shared__ float sm[];
    float* sG1T  = sm;              // 512  [k][i] transposed
    float* sB1   = sG1T + 512;      // 64
    float* sG2T  = sB1 + 64;        // 4096 [k][i]
    float* sB2   = sG2T + 4096;     // 64
    float* sG3T  = sB2 + 64;        // 4096
    float* sB3   = sG3T + 4096;     // 64
    float* sAs   = sB3 + 64;        // 8*TE  [feat][tid]
    float* sAd   = sAs + 8 * TE;    // 8*TE
    float* sBias = sAd + 8 * TE;    // 128
    float* sChunk = sBias + 128;    // 128*68 column-major [c][k], stride 68 (272B: 16B-aligned)

    int tid = threadIdx.x;
    // stage small MLP weights (transposed: row = output k, contiguous over input i)
    for (int idx = tid; idx < 512; idx += TE) {
        int i = idx >> 6, k = idx & 63;
        sG1T[k * 8 + i] = gw1[idx];
    }
    for (int idx = tid; idx < 4096; idx += TE) {
        int i = idx >> 6, k = idx & 63;
        sG2T[k * 64 + i] = gw2[idx];
        sG3T[k * 64 + i] = gw3[idx];
    }
    if (tid < 64) { sB1[tid] = gb1[tid]; sB2[tid] = gb2[tid]; sB3[tid] = gb3[tid]; }

    int e = blockIdx.x * TE + tid;
    bool valid = e < NE;
    int ee = valid ? e : 0;
    int src = esrc[ee], dst = edst[ee];

    // edge vector (with shift @ cell)
    float s0 = shifts[ee * 3 + 0], s1 = shifts[ee * 3 + 1], s2 = shifts[ee * 3 + 2];
    const float* cb = cell + batch[src] * 9;
    float vx = pos[dst * 3 + 0] - pos[src * 3 + 0] + s0 * cb[0] + s1 * cb[3] + s2 * cb[6];
    float vy = pos[dst * 3 + 1] - pos[src * 3 + 1] + s0 * cb[1] + s1 * cb[4] + s2 * cb[7];
    float vz = pos[dst * 3 + 2] - pos[src * 3 + 2] + s0 * cb[2] + s1 * cb[5] + s2 * cb[8];
    float r  = sqrtf(vx * vx + vy * vy + vz * vz + 1e-12f);
    float ir = __fdividef(1.0f, r);
    float ux = vx * ir, uy = vy * ir, uz = vz * ir;

    // spherical harmonics l=0,1,2
    float sh[9];
    sh[0] = 1.0f;
    sh[1] = 1.7320508075688772f * ux;
    sh[2] = 1.7320508075688772f * uy;
    sh[3] = 1.7320508075688772f * uz;
    sh[4] = 3.872983346207417f * ux * uy;
    sh[5] = 3.872983346207417f * uy * uz;
    sh[6] = 1.118033988749895f * (2.0f * uz * uz - ux * ux - uy * uy);
    sh[7] = 3.872983346207417f * ux * uz;
    sh[8] = 1.9364916731037085f * (ux * ux - uy * uy);

    // radial gaussian embedding (NB=8, sigma=1/7, * sqrt(8), cutoff) -> packed
    float xr = fminf(r * 0.2f, 1.0f);
    float mk = (r <= 5.0f) ? 2.8284271247461903f : 0.0f;
    float emb[8];
    #pragma unroll
    for (int j = 0; j < 8; j++) {
        float t = (xr - (float)j * (1.0f / 7.0f)) * 7.0f;
        emb[j] = __expf(-0.5f * t * t) * mk;
    }
    u64 embp[4];
    #pragma unroll
    for (int j = 0; j < 4; j++) embp[j] = fpack(emb[2 * j], emb[2 * j + 1]);

    // gathered atom features -> smem ([feat][tid], self-read only)
    float4 as0 = *(const float4*)(g_Ai + src * 8);
    float4 as1 = *(const float4*)(g_Ai + src * 8 + 4);
    float4 ad0 = *(const float4*)(g_Ai + dst * 8);
    float4 ad1 = *(const float4*)(g_Ai + dst * 8 + 4);
    sAs[0 * TE + tid] = as0.x; sAs[1 * TE + tid] = as0.y; sAs[2 * TE + tid] = as0.z; sAs[3 * TE + tid] = as0.w;
    sAs[4 * TE + tid] = as1.x; sAs[5 * TE + tid] = as1.y; sAs[6 * TE + tid] = as1.z; sAs[7 * TE + tid] = as1.w;
    sAd[0 * TE + tid] = ad0.x; sAd[1 * TE + tid] = ad0.y; sAd[2 * TE + tid] = ad0.z; sAd[3 * TE + tid] = ad0.w;
    sAd[4 * TE + tid] = ad1.x; sAd[5 * TE + tid] = ad1.y; sAd[6 * TE + tid] = ad1.z; sAd[7 * TE + tid] = ad1.w;

    __syncthreads();   // weight staging complete

    // radial MLP layer 1 (8 -> 64), packed over input
    u64 h1[32];
    #pragma unroll
    for (int k = 0; k < 64; k += 2) {
        float o[2];
        #pragma unroll
        for (int kk = 0; kk < 2; kk++) {
            const u64* wr = (const u64*)(sG1T + (k + kk) * 8);
            ulonglong2 w01 = *(const ulonglong2*)(wr);
            ulonglong2 w23 = *(const ulonglong2*)(wr + 2);
            u64 a0 = f2mul(w01.x, embp[0]);
            u64 a1 = f2mul(w01.y, embp[1]);
            a0 = f2fma(w23.x, embp[2], a0);
            a1 = f2fma(w23.y, embp[3], a1);
            u64 s = f2add(a0, a1);
            float2 sv = funpack(s);
            o[kk] = silu_f(sv.x + sv.y + sB1[k + kk]);
        }
        h1[k >> 1] = fpack(o[0], o[1]);
    }
    u64 h2[32];
    layer64p(sG2T, sB2, h1, h2);
    u64 h3[32];
    layer64p(sG3T, sB3, h2, h3);

    // fused final layer + tensor-product contraction over 8 gw4 chunks
    u64 g[16];
    #pragma unroll
    for (int i = 0; i < 16; i++) g[i] = 0ull;

    #pragma unroll 1
    for (int ch = 0; ch < 8; ch++) {
        __syncthreads();                 // previous chunk fully consumed
        int cbase = ch << 7;
        #pragma unroll
        for (int t2 = 0; t2 < 32; t2++) {  // 64*128/TE
            int idx = t2 * TE + tid;
            int k = idx >> 7, c = idx & 127;
            sChunk[c * 68 + k] = gw4[k * 1024 + cbase + c];   // coalesced read
        }
        if (tid < 128) sBias[tid] = gb4[cbase + tid];
        __syncthreads();

        if (ch < 4)       chunk_accum<8, 0>(sChunk, sBias, sAs, sAd, tid, ch * 16, h3, g);
        else if (ch < 6)  chunk_accum<4, 8>(sChunk, sBias, sAs, sAd, tid, (ch - 4) * 32, h3, g);
        else              chunk_accum<4, 12>(sChunk, sBias, sAs, sAd, tid, (ch - 6) * 32, h3, g);
    }

    // scatter: edge_features = alpha * g[u] * sh[m]
    if (valid) {
        float gs[16];
        #pragma unroll
        for (int u = 0; u < 16; u++) {
            float2 gv = funpack(g[u]);
            gs[u] = gv.x + gv.y;
        }
        float* o = out + dst * 40;
        const float alpha = 0.125f;
        #pragma unroll
        for (int u = 0; u < 8; u++) atomicAdd(o + u, alpha * gs[u]);           // sh[0] = 1
        #pragma unroll
        for (int u = 0; u < 4; u++)
            #pragma unroll
            for (int m = 0; m < 3; m++)
                atomicAdd(o + 8 + u * 3 + m, alpha * gs[8 + u] * sh[1 + m]);
        #pragma unroll
        for (int u = 0; u < 4; u++)
            #pragma unroll
            for (int m = 0; m < 5; m++)
                atomicAdd(o + 20 + u * 5 + m, alpha * gs[12 + u] * sh[4 + m]);
        atomicAdd(&g_cnt[dst], 1.0f);
    }
}

// ---------------------------------------------------------------- normalize (segment mean)
__global__ void norm_kernel(float* __restrict__ out) {
    int i = blockIdx.x * 256 + threadIdx.x;
    if (i < NN * 40) {
        float c = g_cnt[i / 40];
        out[i] = out[i] / fmaxf(c, 1.0f);
    }
}

// ---------------------------------------------------------------- launch
extern "C" void kernel_launch(void* const* d_in, const int* in_sizes, int n_in,
                              void* d_out, int out_size)
{
    const float* pos        = (const float*)d_in[0];
    const float* shifts     = (const float*)d_in[1];
    const float* cell       = (const float*)d_in[2];
    const float* atom_table = (const float*)d_in[3];
    const float* fw1 = (const float*)d_in[4];  const float* fb1 = (const float*)d_in[5];
    const float* fw2 = (const float*)d_in[6];  const float* fb2 = (const float*)d_in[7];
    const float* fw3 = (const float*)d_in[8];  const float* fb3 = (const float*)d_in[9];
    const float* gw1 = (const float*)d_in[10]; const float* gb1 = (const float*)d_in[11];
    const float* gw2 = (const float*)d_in[12]; const float* gb2 = (const float*)d_in[13];
    const float* gw3 = (const float*)d_in[14]; const float* gb3 = (const float*)d_in[15];
    const float* gw4 = (const float*)d_in[16]; const float* gb4 = (const float*)d_in[17];
    const int* A     = (const int*)d_in[18];
    const int* batch = (const int*)d_in[19];
    const int* esrc  = (const int*)d_in[20];
    const int* edst  = (const int*)d_in[21];
    float* out = (float*)d_out;

    const int SMEM_EDGE = 21824 * 4;  // 87296 bytes
    cudaFuncSetAttribute(edge_kernel, cudaFuncAttributeMaxDynamicSharedMemorySize, SMEM_EDGE);

    zero_kernel<<<(NN * 40 + 255) / 256, 256>>>(out);
    atom_kernel<<<(NN + 255) / 256, 256>>>(atom_table, fw1, fb1, fw2, fb2, fw3, fb3, A);
    edge_kernel<<<(NE + TE - 1) / TE, TE, SMEM_EDGE>>>(pos, shifts, cell,
                                                       gw1, gb1, gw2, gb2, gw3, gb3, gw4, gb4,
                                                       batch, esrc, edst, out);
    norm_kernel<<<(NN * 40 + 255) / 256, 256>>>(out);
}